// round 7
// baseline (speedup 1.0000x reference)
#include <cuda_runtime.h>
#include <cuda_bf16.h>

#define FULLMASK 0xffffffffu
#define MAXL 32

// HierarchicalSoftmax. TWO warps per sample, split over the D dimension
// (each warp owns 256 of 512 dims) — W/emb traffic is partitioned, not
// duplicated. Each warp computes 32 partial step-dots via register butterfly,
// halves are combined through 128B of smem, warp 0 of the pair runs the epilogue.
// Path validity from data: Huffman root id 0 is the LAST valid entry of every
// path; padding is also 0 -> active[l] = (l<L) && (l==0 || node[l-1]!=0).

__device__ __forceinline__ void hs_butterfly16(float (&acc)[16], int lane)
{
    #pragma unroll
    for (int h = 8; h >= 1; h >>= 1) {
        #pragma unroll
        for (int i = 0; i < h; ++i) {
            float v = acc[i], w = acc[i + h];
            float give = (lane & h) ? v : w;
            float got  = __shfl_xor_sync(FULLMASK, give, h);
            acc[i] = ((lane & h) ? w : v) + got;
        }
    }
}

__global__ __launch_bounds__(128, 8)
void hs512_dsplit_kernel(const float* __restrict__ emb,
                         const float* __restrict__ W,
                         const float* __restrict__ bias,
                         const int*   __restrict__ target,
                         const int*   __restrict__ path_nodes,
                         const int*   __restrict__ path_dirs,
                         float*       __restrict__ out,
                         int B, int L)
{
    __shared__ float part[4][32];                  // per-warp partial step-dots

    const int D4 = 512 / 4;                        // 128 float4 per row
    int wid  = threadIdx.x >> 5;                   // 0..3
    int lane = threadIdx.x & 31;
    int gw   = blockIdx.x * 2 + (wid >> 1);        // sample index (2 per block)
    int half = wid & 1;                            // which 256-dim half
    bool valid = (gw < B);

    float4 e0, e1;
    const int* nrow = nullptr;
    const int* drow = nullptr;
    int my_node = 0, my_dir = 0;
    bool act = false;
    unsigned am = 0;

    int off = half * 64;                           // float4 offset of this half

    if (valid) {
        // This warp's 256-dim half of the embedding: 2 float4 per lane.
        const float4* e4 = reinterpret_cast<const float4*>(emb) + (size_t)gw * D4;
        e0 = e4[off + lane];
        e1 = e4[off + lane + 32];

        int t = __ldg(target + gw);
        nrow = path_nodes + (size_t)t * L;
        drow = path_dirs  + (size_t)t * L;

        // Coalesced per-lane node/dir: lane l owns path step l.
        my_node = (lane < L) ? __ldg(nrow + lane) : 0;
        my_dir  = (lane < L) ? __ldg(drow + lane) : 0;

        int prev = __shfl_up_sync(FULLMASK, my_node, 1);
        act = (lane < L) && (lane == 0 || prev != 0);
        am  = __ballot_sync(FULLMASK, act);
    }

    const float4* W4 = reinterpret_cast<const float4*>(W);

    float accA[16], accB[16];
    unsigned amB = am >> 16;

    if (valid) {
        // Phase 1: all W half-row loads in one batch (2 LDG.128 per step).
        #pragma unroll
        for (int i = 0; i < 16; ++i) {
            float s = 0.0f;
            if ((am >> i) & 1u) {
                int node = __shfl_sync(FULLMASK, my_node, i);
                const float4* w4 = W4 + (size_t)node * 128 + off;
                float4 w0 = w4[lane];
                float4 w1 = w4[lane + 32];
                s = e0.x * w0.x;
                s = fmaf(e0.y, w0.y, s); s = fmaf(e0.z, w0.z, s); s = fmaf(e0.w, w0.w, s);
                s = fmaf(e1.x, w1.x, s); s = fmaf(e1.y, w1.y, s);
                s = fmaf(e1.z, w1.z, s); s = fmaf(e1.w, w1.w, s);
            }
            accA[i] = s;
        }
        if (amB) {
            #pragma unroll
            for (int i = 0; i < 16; ++i) {
                float s = 0.0f;
                if ((amB >> i) & 1u) {
                    int node = __shfl_sync(FULLMASK, my_node, 16 + i);
                    const float4* w4 = W4 + (size_t)node * 128 + off;
                    float4 w0 = w4[lane];
                    float4 w1 = w4[lane + 32];
                    s = e0.x * w0.x;
                    s = fmaf(e0.y, w0.y, s); s = fmaf(e0.z, w0.z, s); s = fmaf(e0.w, w0.w, s);
                    s = fmaf(e1.x, w1.x, s); s = fmaf(e1.y, w1.y, s);
                    s = fmaf(e1.z, w1.z, s); s = fmaf(e1.w, w1.w, s);
                }
                accB[i] = s;
            }
        }

        // Phase 2: butterflies -> lane l holds this warp's partial dot of step l.
        hs_butterfly16(accA, lane);
        float sA = accA[0] + __shfl_xor_sync(FULLMASK, accA[0], 16);
        float sB = 0.0f;
        if (amB) {
            hs_butterfly16(accB, lane);
            sB = accB[0] + __shfl_xor_sync(FULLMASK, accB[0], 16);
        }
        part[wid][lane] = (lane < 16) ? sA : sB;
    }

    __syncthreads();

    // Epilogue: warp 0 of each pair combines halves; one sigmoid per lane.
    if (valid && half == 0) {
        float dotv = part[wid][lane] + part[wid + 1][lane];
        float f = 1.0f;
        if (act) {
            float sc = dotv + __ldg(bias + my_node);
            float sg = my_dir ? sc : -sc;
            f = __fdividef(1.0f, 1.0f + __expf(-sg));
        }
        #pragma unroll
        for (int o = 16; o >= 1; o >>= 1)
            f *= __shfl_xor_sync(FULLMASK, f, o);
        if (lane == 0) out[gw] = f;
    }
}

// Generic fallback (any D, any L) — shape safety, not the hot path.
__global__ __launch_bounds__(256)
void hs_generic_kernel(const float* __restrict__ emb,
                       const float* __restrict__ W,
                       const float* __restrict__ bias,
                       const int*   __restrict__ target,
                       const int*   __restrict__ path_nodes,
                       const int*   __restrict__ path_dirs,
                       float*       __restrict__ out,
                       int B, int D, int L)
{
    int gw   = (blockIdx.x * blockDim.x + threadIdx.x) >> 5;
    int lane = threadIdx.x & 31;
    if (gw >= B) return;

    const float* e = emb + (size_t)gw * D;
    int t = __ldg(target + gw);
    const int* nrow = path_nodes + (size_t)t * L;
    const int* drow = path_dirs  + (size_t)t * L;

    float prod = 1.0f;
    for (int l = 0; l < L; ++l) {
        int node = __ldg(nrow + l);
        int dir  = __ldg(drow + l);
        const float* w = W + (size_t)node * D;
        float acc = 0.0f;
        for (int d = lane; d < D; d += 32)
            acc = fmaf(e[d], w[d], acc);
        #pragma unroll
        for (int offr = 16; offr > 0; offr >>= 1)
            acc += __shfl_xor_sync(FULLMASK, acc, offr);
        float s  = acc + __ldg(bias + node);
        float sg = dir ? s : -s;
        prod *= __fdividef(1.0f, 1.0f + __expf(-sg));
        if (node == 0) break;
    }
    if (lane == 0) out[gw] = prod;
}

extern "C" void kernel_launch(void* const* d_in, const int* in_sizes, int n_in,
                              void* d_out, int out_size)
{
    const float* emb    = (const float*)d_in[0];   // [B, D] f32
    const float* W      = (const float*)d_in[1];   // [V-1, D] f32
    const float* bias   = (const float*)d_in[2];   // [V-1] f32
    const int*   target = (const int*)  d_in[3];   // [B] i32
    const int*   nodes  = (const int*)  d_in[4];   // [V, L] i32
    const int*   dirs   = (const int*)  d_in[5];   // [V, L] i32
    // d_in[6] = path_mask: unused (validity derived from node==0 sentinel)

    int B = in_sizes[3];
    int D = in_sizes[0] / B;
    int V = in_sizes[2] + 1;
    int L = in_sizes[4] / V;
    float* out = (float*)d_out;

    if (D == 512 && L <= MAXL) {
        int blocks = (B + 1) / 2;                  // 2 samples x 2 warps per block
        hs512_dsplit_kernel<<<blocks, 128>>>(emb, W, bias, target, nodes, dirs, out, B, L);
    } else {
        int threads = 256;
        int blocks  = (B * 32 + threads - 1) / threads;
        hs_generic_kernel<<<blocks, threads>>>(emb, W, bias, target, nodes, dirs, out, B, D, L);
    }
}

// round 8
// speedup vs baseline: 1.3113x; 1.3113x over previous
#include <cuda_runtime.h>
#include <cuda_bf16.h>

#define FULLMASK 0xffffffffu
#define MAXL 32

// HierarchicalSoftmax. One warp per sample. Path processed in FOUR chunks of 8
// steps: each chunk = one batched burst of W-row loads (16 LDG.128) + an 8-acc
// register butterfly (strides 4,2,1) + cross-group combine, so lane l ends up
// holding the full dot product of step (l & 7) of that chunk. Chunk bursts are
// register-independent -> the scheduler overlaps chunk n+1's loads with chunk
// n's reduction, while each individual burst stays small enough to be
// L1tex-queue friendly.
// Path validity from data: Huffman root id 0 is the LAST valid entry of every
// path; padding is also 0 -> active[l] = (l<L) && (l==0 || node[l-1]!=0).

__device__ __forceinline__ float hs_chunk8(const float4* __restrict__ W4,
                                           unsigned am8,      // uniform 8-bit mask
                                           int base, int my_node, int lane,
                                           float4 e0, float4 e1, float4 e2, float4 e3)
{
    float acc[8];
    #pragma unroll
    for (int i = 0; i < 8; ++i) {
        float s = 0.0f;
        if ((am8 >> i) & 1u) {                       // warp-uniform
            int node = __shfl_sync(FULLMASK, my_node, base + i);
            const float4* w4 = W4 + (size_t)node * 128;
            float4 w0 = w4[lane +  0];
            float4 w1 = w4[lane + 32];
            float4 w2 = w4[lane + 64];
            float4 w3 = w4[lane + 96];
            s = e0.x * w0.x;
            s = fmaf(e0.y, w0.y, s); s = fmaf(e0.z, w0.z, s); s = fmaf(e0.w, w0.w, s);
            s = fmaf(e1.x, w1.x, s); s = fmaf(e1.y, w1.y, s);
            s = fmaf(e1.z, w1.z, s); s = fmaf(e1.w, w1.w, s);
            s = fmaf(e2.x, w2.x, s); s = fmaf(e2.y, w2.y, s);
            s = fmaf(e2.z, w2.z, s); s = fmaf(e2.w, w2.w, s);
            s = fmaf(e3.x, w3.x, s); s = fmaf(e3.y, w3.y, s);
            s = fmaf(e3.z, w3.z, s); s = fmaf(e3.w, w3.w, s);
        }
        acc[i] = s;
    }
    // Butterfly over 8 accs, strides 4..1: stays within each 8-lane group;
    // afterwards lane l holds the group-sum of step (l & 7).
    #pragma unroll
    for (int h = 4; h >= 1; h >>= 1) {
        #pragma unroll
        for (int i = 0; i < h; ++i) {
            float v = acc[i], w = acc[i + h];
            float give = (lane & h) ? v : w;
            float got  = __shfl_xor_sync(FULLMASK, give, h);
            acc[i] = ((lane & h) ? w : v) + got;
        }
    }
    // Combine the four 8-lane groups -> full 32-lane dot of step (l & 7).
    acc[0] += __shfl_xor_sync(FULLMASK, acc[0], 8);
    acc[0] += __shfl_xor_sync(FULLMASK, acc[0], 16);
    return acc[0];
}

__global__ __launch_bounds__(128, 6)
void hs512_v8_kernel(const float* __restrict__ emb,
                     const float* __restrict__ W,
                     const float* __restrict__ bias,
                     const int*   __restrict__ target,
                     const int*   __restrict__ path_nodes,
                     const int*   __restrict__ path_dirs,
                     float*       __restrict__ out,
                     int B, int L)
{
    const int D4 = 512 / 4;                                    // 128 float4 per row
    int gw   = (blockIdx.x * blockDim.x + threadIdx.x) >> 5;   // one warp per sample
    int lane = threadIdx.x & 31;
    if (gw >= B) return;

    // Embedding row in registers: 4x float4 per lane, coalesced.
    const float4* e4 = reinterpret_cast<const float4*>(emb) + (size_t)gw * D4;
    float4 e0 = e4[lane +  0];
    float4 e1 = e4[lane + 32];
    float4 e2 = e4[lane + 64];
    float4 e3 = e4[lane + 96];

    int t = __ldg(target + gw);
    const int* nrow = path_nodes + (size_t)t * L;
    const int* drow = path_dirs  + (size_t)t * L;

    // Coalesced per-lane node/dir loads: lane l owns path step l.
    int my_node = (lane < L) ? __ldg(nrow + lane) : 0;
    int my_dir  = (lane < L) ? __ldg(drow + lane) : 0;

    // Active mask via shfl_up + ballot (root id 0 terminates the path).
    int prev = __shfl_up_sync(FULLMASK, my_node, 1);
    bool act = (lane < L) && (lane == 0 || prev != 0);
    unsigned am = __ballot_sync(FULLMASK, act);

    const float4* W4 = reinterpret_cast<const float4*>(W);

    // Four chunks of 8 steps; warp-uniform skip once past the path end.
    float s0 = hs_chunk8(W4, am & 0xffu, 0, my_node, lane, e0, e1, e2, e3);
    float s1 = 0.0f, s2 = 0.0f, s3 = 0.0f;
    if (am >> 8) {
        s1 = hs_chunk8(W4, (am >> 8) & 0xffu, 8, my_node, lane, e0, e1, e2, e3);
        if (am >> 16) {
            s2 = hs_chunk8(W4, (am >> 16) & 0xffu, 16, my_node, lane, e0, e1, e2, e3);
            if (am >> 24)
                s3 = hs_chunk8(W4, (am >> 24) & 0xffu, 24, my_node, lane, e0, e1, e2, e3);
        }
    }

    // Epilogue: lane l needs step l = 8*(l>>3) + (l&7); chunk result c holds
    // step (l & 7)'s dot on every lane -> select by lane's chunk index.
    float dotv = (lane < 8) ? s0 : (lane < 16) ? s1 : (lane < 24) ? s2 : s3;
    float f = 1.0f;
    if (act) {
        float sc = dotv + __ldg(bias + my_node);
        float sg = my_dir ? sc : -sc;
        f = __fdividef(1.0f, 1.0f + __expf(-sg));
    }
    #pragma unroll
    for (int o = 16; o >= 1; o >>= 1)
        f *= __shfl_xor_sync(FULLMASK, f, o);

    if (lane == 0) out[gw] = f;
}

// Generic fallback (any D, any L) — shape safety, not the hot path.
__global__ __launch_bounds__(256)
void hs_generic_kernel(const float* __restrict__ emb,
                       const float* __restrict__ W,
                       const float* __restrict__ bias,
                       const int*   __restrict__ target,
                       const int*   __restrict__ path_nodes,
                       const int*   __restrict__ path_dirs,
                       float*       __restrict__ out,
                       int B, int D, int L)
{
    int gw   = (blockIdx.x * blockDim.x + threadIdx.x) >> 5;
    int lane = threadIdx.x & 31;
    if (gw >= B) return;

    const float* e = emb + (size_t)gw * D;
    int t = __ldg(target + gw);
    const int* nrow = path_nodes + (size_t)t * L;
    const int* drow = path_dirs  + (size_t)t * L;

    float prod = 1.0f;
    for (int l = 0; l < L; ++l) {
        int node = __ldg(nrow + l);
        int dir  = __ldg(drow + l);
        const float* w = W + (size_t)node * D;
        float acc = 0.0f;
        for (int d = lane; d < D; d += 32)
            acc = fmaf(e[d], w[d], acc);
        #pragma unroll
        for (int off = 16; off > 0; off >>= 1)
            acc += __shfl_xor_sync(FULLMASK, acc, off);
        float s  = acc + __ldg(bias + node);
        float sg = dir ? s : -s;
        prod *= __fdividef(1.0f, 1.0f + __expf(-sg));
        if (node == 0) break;
    }
    if (lane == 0) out[gw] = prod;
}

extern "C" void kernel_launch(void* const* d_in, const int* in_sizes, int n_in,
                              void* d_out, int out_size)
{
    const float* emb    = (const float*)d_in[0];   // [B, D] f32
    const float* W      = (const float*)d_in[1];   // [V-1, D] f32
    const float* bias   = (const float*)d_in[2];   // [V-1] f32
    const int*   target = (const int*)  d_in[3];   // [B] i32
    const int*   nodes  = (const int*)  d_in[4];   // [V, L] i32
    const int*   dirs   = (const int*)  d_in[5];   // [V, L] i32
    // d_in[6] = path_mask: unused (validity derived from node==0 sentinel)

    int B = in_sizes[3];
    int D = in_sizes[0] / B;
    int V = in_sizes[2] + 1;
    int L = in_sizes[4] / V;
    float* out = (float*)d_out;

    if (D == 512 && L <= MAXL) {
        int threads = 128;                         // 4 warps = 4 samples per block
        int blocks  = (B * 32 + threads - 1) / threads;
        hs512_v8_kernel<<<blocks, threads>>>(emb, W, bias, target, nodes, dirs, out, B, L);
    } else {
        int threads = 256;
        int blocks  = (B * 32 + threads - 1) / threads;
        hs_generic_kernel<<<blocks, threads>>>(emb, W, bias, target, nodes, dirs, out, B, D, L);
    }
}

// round 9
// speedup vs baseline: 1.3442x; 1.0251x over previous
#include <cuda_runtime.h>
#include <cuda_bf16.h>

#define FULLMASK 0xffffffffu
#define MAXL 32

// HierarchicalSoftmax. One warp per sample; two 16-step chunks, each a batched
// W-row load burst + 16-acc register butterfly that transposes step-sums onto
// lanes (lane l ends with the dot product of step l). __launch_bounds__(128,7)
// makes all 1024 blocks (4096 warps) resident in ONE wave (148 SM x 7 blocks),
// eliminating the second-wave tail seen at 6 blocks/SM.
// Path validity from data: Huffman root id 0 is the LAST valid entry of every
// path; padding is also 0 -> active[l] = (l<L) && (l==0 || node[l-1]!=0).

__device__ __forceinline__ float hs_dot16(const float4* __restrict__ W4,
                                          unsigned am, int base, int my_node,
                                          int lane,
                                          float4 e0, float4 e1, float4 e2, float4 e3)
{
    float acc[16];
    #pragma unroll
    for (int i = 0; i < 16; ++i) {
        float s = 0.0f;
        if ((am >> (base + i)) & 1u) {               // warp-uniform (prefix mask)
            int node = __shfl_sync(FULLMASK, my_node, base + i);
            const float4* w4 = W4 + (size_t)node * 128;
            float4 w0 = w4[lane +  0];
            float4 w1 = w4[lane + 32];
            float4 w2 = w4[lane + 64];
            float4 w3 = w4[lane + 96];
            s = e0.x * w0.x;
            s = fmaf(e0.y, w0.y, s); s = fmaf(e0.z, w0.z, s); s = fmaf(e0.w, w0.w, s);
            s = fmaf(e1.x, w1.x, s); s = fmaf(e1.y, w1.y, s);
            s = fmaf(e1.z, w1.z, s); s = fmaf(e1.w, w1.w, s);
            s = fmaf(e2.x, w2.x, s); s = fmaf(e2.y, w2.y, s);
            s = fmaf(e2.z, w2.z, s); s = fmaf(e2.w, w2.w, s);
            s = fmaf(e3.x, w3.x, s); s = fmaf(e3.y, w3.y, s);
            s = fmaf(e3.z, w3.z, s); s = fmaf(e3.w, w3.w, s);
        }
        acc[i] = s;
    }
    // Butterfly: strides 8..1 reduce within each 16-lane half; afterwards lane l
    // holds the half-sum of step (l & 15). Stride-16 combine -> full dot product.
    #pragma unroll
    for (int h = 8; h >= 1; h >>= 1) {
        #pragma unroll
        for (int i = 0; i < h; ++i) {
            float v = acc[i], w = acc[i + h];
            float give = (lane & h) ? v : w;
            float got  = __shfl_xor_sync(FULLMASK, give, h);
            acc[i] = ((lane & h) ? w : v) + got;
        }
    }
    return acc[0] + __shfl_xor_sync(FULLMASK, acc[0], 16);
}

__global__ __launch_bounds__(128, 7)
void hs512_v9_kernel(const float* __restrict__ emb,
                     const float* __restrict__ W,
                     const float* __restrict__ bias,
                     const int*   __restrict__ target,
                     const int*   __restrict__ path_nodes,
                     const int*   __restrict__ path_dirs,
                     float*       __restrict__ out,
                     int B, int L)
{
    const int D4 = 512 / 4;                                    // 128 float4 per row
    int gw   = (blockIdx.x * blockDim.x + threadIdx.x) >> 5;   // one warp per sample
    int lane = threadIdx.x & 31;
    if (gw >= B) return;

    // Embedding row in registers: 4x float4 per lane, coalesced.
    const float4* e4 = reinterpret_cast<const float4*>(emb) + (size_t)gw * D4;
    float4 e0 = e4[lane +  0];
    float4 e1 = e4[lane + 32];
    float4 e2 = e4[lane + 64];
    float4 e3 = e4[lane + 96];

    int t = __ldg(target + gw);
    const int* nrow = path_nodes + (size_t)t * L;
    const int* drow = path_dirs  + (size_t)t * L;

    // Coalesced per-lane node/dir loads: lane l owns path step l.
    int my_node = (lane < L) ? __ldg(nrow + lane) : 0;
    int my_dir  = (lane < L) ? __ldg(drow + lane) : 0;

    // Active mask via shfl_up + ballot (root id 0 terminates the path).
    int prev = __shfl_up_sync(FULLMASK, my_node, 1);
    bool act = (lane < L) && (lane == 0 || prev != 0);
    unsigned am = __ballot_sync(FULLMASK, act);

    const float4* W4 = reinterpret_cast<const float4*>(W);

    // Chunk A: steps 0..15. Lane l gets dot of step (l & 15).
    float sA = hs_dot16(W4, am, 0, my_node, lane, e0, e1, e2, e3);

    // Chunk B: steps 16..31 — warp-uniform skip when the path is short.
    float sB = 0.0f;
    if (am >> 16)
        sB = hs_dot16(W4, am, 16, my_node, lane, e0, e1, e2, e3);

    // Epilogue: lane l holds step l's dot (sA for l<16, sB for l>=16 since
    // base + (l & 15) == l). One bias gather + one sigmoid per active lane.
    float dotv = (lane < 16) ? sA : sB;
    float f = 1.0f;
    if (act) {
        float sc = dotv + __ldg(bias + my_node);
        float sg = my_dir ? sc : -sc;
        f = __fdividef(1.0f, 1.0f + __expf(-sg));
    }
    #pragma unroll
    for (int o = 16; o >= 1; o >>= 1)
        f *= __shfl_xor_sync(FULLMASK, f, o);

    if (lane == 0) out[gw] = f;
}

// Generic fallback (any D, any L) — shape safety, not the hot path.
__global__ __launch_bounds__(256)
void hs_generic_kernel(const float* __restrict__ emb,
                       const float* __restrict__ W,
                       const float* __restrict__ bias,
                       const int*   __restrict__ target,
                       const int*   __restrict__ path_nodes,
                       const int*   __restrict__ path_dirs,
                       float*       __restrict__ out,
                       int B, int D, int L)
{
    int gw   = (blockIdx.x * blockDim.x + threadIdx.x) >> 5;
    int lane = threadIdx.x & 31;
    if (gw >= B) return;

    const float* e = emb + (size_t)gw * D;
    int t = __ldg(target + gw);
    const int* nrow = path_nodes + (size_t)t * L;
    const int* drow = path_dirs  + (size_t)t * L;

    float prod = 1.0f;
    for (int l = 0; l < L; ++l) {
        int node = __ldg(nrow + l);
        int dir  = __ldg(drow + l);
        const float* w = W + (size_t)node * D;
        float acc = 0.0f;
        for (int d = lane; d < D; d += 32)
            acc = fmaf(e[d], w[d], acc);
        #pragma unroll
        for (int off = 16; off > 0; off >>= 1)
            acc += __shfl_xor_sync(FULLMASK, acc, off);
        float s  = acc + __ldg(bias + node);
        float sg = dir ? s : -s;
        prod *= __fdividef(1.0f, 1.0f + __expf(-sg));
        if (node == 0) break;
    }
    if (lane == 0) out[gw] = prod;
}

extern "C" void kernel_launch(void* const* d_in, const int* in_sizes, int n_in,
                              void* d_out, int out_size)
{
    const float* emb    = (const float*)d_in[0];   // [B, D] f32
    const float* W      = (const float*)d_in[1];   // [V-1, D] f32
    const float* bias   = (const float*)d_in[2];   // [V-1] f32
    const int*   target = (const int*)  d_in[3];   // [B] i32
    const int*   nodes  = (const int*)  d_in[4];   // [V, L] i32
    const int*   dirs   = (const int*)  d_in[5];   // [V, L] i32
    // d_in[6] = path_mask: unused (validity derived from node==0 sentinel)

    int B = in_sizes[3];
    int D = in_sizes[0] / B;
    int V = in_sizes[2] + 1;
    int L = in_sizes[4] / V;
    float* out = (float*)d_out;

    if (D == 512 && L <= MAXL) {
        int threads = 128;                         // 4 warps = 4 samples per block
        int blocks  = (B * 32 + threads - 1) / threads;
        hs512_v9_kernel<<<blocks, threads>>>(emb, W, bias, target, nodes, dirs, out, B, L);
    } else {
        int threads = 256;
        int blocks  = (B * 32 + threads - 1) / threads;
        hs_generic_kernel<<<blocks, threads>>>(emb, W, bias, target, nodes, dirs, out, B, D, L);
    }
}